// round 2
// baseline (speedup 1.0000x reference)
#include <cuda_runtime.h>

// CentDif: 6th-order central difference along last axis + 2-channel advection combine.
// u: [M=16384, N=2, L=2048] fp32; out same shape.
// out[:,0,l] = -(u1*du0 + u0*du1);  out[:,1,l] = -(2*du0 + u1*du1)
// du zero in ghost region (l < 10 or l >= L-10)  =>  out zero there too.

#define M_DIM 16384
#define L_DIM 2048
#define IGST  10
#define NTHREADS 256

__global__ __launch_bounds__(NTHREADS) void centdif_kernel(
    const float* __restrict__ u, float* __restrict__ out)
{
    __shared__ float s0[L_DIM];
    __shared__ float s1[L_DIM];

    const int m = blockIdx.x;
    const size_t base = (size_t)m * (2 * L_DIM);
    const float4* __restrict__ u0v = (const float4*)(u + base);
    const float4* __restrict__ u1v = (const float4*)(u + base + L_DIM);

    // Stage both channel rows in smem (vectorized, coalesced; each global
    // element touched exactly once).
    for (int j = threadIdx.x; j < L_DIM / 4; j += NTHREADS) {
        ((float4*)s0)[j] = u0v[j];
        ((float4*)s1)[j] = u1v[j];
    }
    __syncthreads();

    const float c = (float)(1.0 / (60.0 * 0.012));  // 1/(60*DX)

    float* __restrict__ o0 = out + base;
    float* __restrict__ o1 = out + base + L_DIM;

    // Thread-stride-1 compute: conflict-free smem reads, coalesced STG.32.
    #pragma unroll
    for (int j = 0; j < L_DIM / NTHREADS; ++j) {
        const int l = threadIdx.x + j * NTHREADS;
        float du0 = 0.0f, du1 = 0.0f;
        if (l >= IGST && l < L_DIM - IGST) {
            du0 = (-s0[l - 3] + 9.0f * s0[l - 2] - 45.0f * s0[l - 1]
                   + 45.0f * s0[l + 1] - 9.0f * s0[l + 2] + s0[l + 3]) * c;
            du1 = (-s1[l - 3] + 9.0f * s1[l - 2] - 45.0f * s1[l - 1]
                   + 45.0f * s1[l + 1] - 9.0f * s1[l + 2] + s1[l + 3]) * c;
        }
        const float a = s0[l];
        const float b = s1[l];
        o0[l] = -(b * du0 + a * du1);
        o1[l] = -(2.0f * du0 + b * du1);
    }
}

extern "C" void kernel_launch(void* const* d_in, const int* in_sizes, int n_in,
                              void* d_out, int out_size)
{
    const float* u = (const float*)d_in[0];
    float* out = (float*)d_out;
    centdif_kernel<<<M_DIM, NTHREADS>>>(u, out);
}

// round 3
// speedup vs baseline: 1.0413x; 1.0413x over previous
#include <cuda_runtime.h>

// CentDif: 6th-order central difference along last axis + 2-channel advection combine.
// u: [M=16384, N=2, L=2048] fp32; out same shape.
// Vectorized: each thread owns 8 consecutive outputs; halo window loaded as
// 4x LDS.128 per channel; results stored as 2x STG.128 per channel.

#define M_DIM 16384
#define L_DIM 2048
#define IGST  10
#define NTHREADS 256   // 256 * 8 = 2048 = L_DIM

__global__ __launch_bounds__(NTHREADS) void centdif_kernel(
    const float* __restrict__ u, float* __restrict__ out)
{
    // +4 leading pad (halo l0-4 for l0=0) and +12 trailing pad (l0+11 for l0=2040),
    // rounded so vector accesses stay in-bounds. Pad values only feed lanes whose
    // du is predicated to zero.
    __shared__ __align__(16) float s0[L_DIM + 16];
    __shared__ __align__(16) float s1[L_DIM + 16];

    const int m = blockIdx.x;
    const size_t base = (size_t)m * (2 * L_DIM);

    // ---- Stage both channel rows into smem at +4 float offset (16B-aligned) ----
    const float4* __restrict__ u0v = (const float4*)(u + base);
    const float4* __restrict__ u1v = (const float4*)(u + base + L_DIM);
    float4* s0v = (float4*)(s0 + 4);
    float4* s1v = (float4*)(s1 + 4);
    #pragma unroll
    for (int j = threadIdx.x; j < L_DIM / 4; j += NTHREADS) {
        s0v[j] = u0v[j];
        s1v[j] = u1v[j];
    }
    __syncthreads();

    const float c = (float)(1.0 / (60.0 * 0.012));  // 1/(60*DX)

    // ---- Each thread: outputs l0 .. l0+7; needs u[l0-4 .. l0+11] per channel ----
    const int l0 = threadIdx.x * 8;

    // a[k] = u0[l0 - 4 + k], k = 0..15  (s0 + l0 is absolute index l0 => rel l0-4)
    float a[16], b[16];
    const float4* p0 = (const float4*)(s0 + l0);  // 16B aligned: l0 % 4 == 0
    const float4* p1 = (const float4*)(s1 + l0);
    #pragma unroll
    for (int q = 0; q < 4; ++q) {
        float4 v0 = p0[q];
        a[4*q + 0] = v0.x; a[4*q + 1] = v0.y; a[4*q + 2] = v0.z; a[4*q + 3] = v0.w;
        float4 v1 = p1[q];
        b[4*q + 0] = v1.x; b[4*q + 1] = v1.y; b[4*q + 2] = v1.z; b[4*q + 3] = v1.w;
    }

    float r0[8], r1[8];
    #pragma unroll
    for (int i = 0; i < 8; ++i) {
        const int l = l0 + i;
        float du0 = 0.0f, du1 = 0.0f;
        if (l >= IGST && l < L_DIM - IGST) {
            // stencil taps: l-3 -> a[i+1], l-2 -> a[i+2], l-1 -> a[i+3],
            //               l+1 -> a[i+5], l+2 -> a[i+6], l+3 -> a[i+7]
            du0 = (-a[i + 1] + 9.0f * a[i + 2] - 45.0f * a[i + 3]
                   + 45.0f * a[i + 5] - 9.0f * a[i + 6] + a[i + 7]) * c;
            du1 = (-b[i + 1] + 9.0f * b[i + 2] - 45.0f * b[i + 3]
                   + 45.0f * b[i + 5] - 9.0f * b[i + 6] + b[i + 7]) * c;
        }
        const float uu0 = a[i + 4];   // u0[l]
        const float uu1 = b[i + 4];   // u1[l]
        r0[i] = -(uu1 * du0 + uu0 * du1);
        r1[i] = -(2.0f * du0 + uu1 * du1);
    }

    // ---- Vectorized stores: 2x float4 per channel ----
    float4* o0 = (float4*)(out + base + l0);
    float4* o1 = (float4*)(out + base + L_DIM + l0);
    o0[0] = make_float4(r0[0], r0[1], r0[2], r0[3]);
    o0[1] = make_float4(r0[4], r0[5], r0[6], r0[7]);
    o1[0] = make_float4(r1[0], r1[1], r1[2], r1[3]);
    o1[1] = make_float4(r1[4], r1[5], r1[6], r1[7]);
}

extern "C" void kernel_launch(void* const* d_in, const int* in_sizes, int n_in,
                              void* d_out, int out_size)
{
    const float* u = (const float*)d_in[0];
    float* out = (float*)d_out;
    centdif_kernel<<<M_DIM, NTHREADS>>>(u, out);
}